// round 6
// baseline (speedup 1.0000x reference)
#include <cuda_runtime.h>
#include <cstdint>

#define N_NODES 100000
#define N_EDGES 1250000
#define D 64
#define NB 196  // ceil(N_NODES / 512) scan blocks

typedef unsigned long long ull;

// ---- device scratch (no allocation allowed) ----
__device__ int g_cnt[N_NODES];       // histogram, then fill cursor
__device__ int g_off[N_NODES + 1];   // CSR offsets
__device__ int g_csr[N_EDGES];       // src node per CSR slot
__device__ int g_bsum[NB];           // scan block sums
__device__ int g_idx_is64;

// ---- f32x2 helpers ----
__device__ __forceinline__ ull pk2(float lo, float hi) {
    ull r;
    asm("mov.b64 %0, {%1, %2};" : "=l"(r) : "f"(lo), "f"(hi));
    return r;
}
__device__ __forceinline__ void upk2(float& lo, float& hi, ull v) {
    asm("mov.b64 {%0, %1}, %2;" : "=f"(lo), "=f"(hi) : "l"(v));
}
#define FMA2(acc, a, b) \
    asm("fma.rn.f32x2 %0, %1, %2, %3;" : "=l"(acc) : "l"(a), "l"(b), "l"(acc))

// ---------------------------------------------------------------------------
// Kernel: zero counters, set g_off[N], detect edge_index dtype.
// int64 little-endian => every odd 32-bit word of values < 100000 is zero.
// ---------------------------------------------------------------------------
__global__ void init_kernel(const int* __restrict__ ei32) {
    int i = blockIdx.x * blockDim.x + threadIdx.x;
    if (i < N_NODES) g_cnt[i] = 0;
    if (blockIdx.x == 0 && threadIdx.x == 0) {
        g_off[N_NODES] = N_EDGES;
        int is64 = 1;
        #pragma unroll 1
        for (int k = 1; k < 128; k += 2) {
            if (ei32[k] != 0) { is64 = 0; break; }
        }
        g_idx_is64 = is64;
    }
}

// ---------------------------------------------------------------------------
// Kernel: histogram of dst.
// ---------------------------------------------------------------------------
__global__ __launch_bounds__(512) void hist_kernel(const void* __restrict__ ei) {
    int e = blockIdx.x * blockDim.x + threadIdx.x;
    if (e >= N_EDGES) return;
    int d;
    if (g_idx_is64) d = (int)__ldg(&((const long long*)ei)[N_EDGES + e]);
    else            d = __ldg(&((const int*)ei)[N_EDGES + e]);
    atomicAdd(&g_cnt[d], 1);
}

// ---------------------------------------------------------------------------
// Scan A: per-512-block sums (warp shuffles).
// ---------------------------------------------------------------------------
__global__ __launch_bounds__(512) void scanA_kernel() {
    __shared__ int wsum[16];
    int t = threadIdx.x;
    int i = blockIdx.x * 512 + t;
    int v = (i < N_NODES) ? g_cnt[i] : 0;
    #pragma unroll
    for (int o = 16; o; o >>= 1) v += __shfl_down_sync(0xffffffffu, v, o);
    if ((t & 31) == 0) wsum[t >> 5] = v;
    __syncthreads();
    if (t < 16) {
        int s = wsum[t];
        #pragma unroll
        for (int o = 8; o; o >>= 1) s += __shfl_down_sync(0xffffu, s, o);
        if (t == 0) g_bsum[blockIdx.x] = s;
    }
}

// ---------------------------------------------------------------------------
// Scan C: base = sum(g_bsum[0..bid)) + local exclusive scan, shuffle-based.
// ---------------------------------------------------------------------------
__global__ __launch_bounds__(512) void scanC_kernel() {
    __shared__ int wsum[16];
    __shared__ int woff[16];
    __shared__ int sbase;
    int t = threadIdx.x, bid = blockIdx.x;
    int lane = t & 31, wid = t >> 5;
    int i = bid * 512 + t;

    // base reduction (bid <= 195 < 512)
    int bv = (t < bid) ? g_bsum[t] : 0;
    #pragma unroll
    for (int o = 16; o; o >>= 1) bv += __shfl_down_sync(0xffffffffu, bv, o);
    if (lane == 0) wsum[wid] = bv;
    __syncthreads();
    if (t < 16) {
        int s = wsum[t];
        #pragma unroll
        for (int o = 8; o; o >>= 1) s += __shfl_down_sync(0xffffu, s, o);
        if (t == 0) sbase = s;
    }
    __syncthreads();

    // local inclusive scan
    int v = (i < N_NODES) ? g_cnt[i] : 0;
    int xi = v;
    #pragma unroll
    for (int o = 1; o < 32; o <<= 1) {
        int y = __shfl_up_sync(0xffffffffu, xi, o);
        if (lane >= o) xi += y;
    }
    if (lane == 31) wsum[wid] = xi;
    __syncthreads();
    if (t < 16) {
        int s = wsum[t];
        int si = s;
        #pragma unroll
        for (int o = 1; o < 16; o <<= 1) {
            int y = __shfl_up_sync(0xffffu, si, o);
            if (t >= o) si += y;
        }
        woff[t] = si - s;  // exclusive warp offset
    }
    __syncthreads();
    if (i < N_NODES) {
        int excl = xi - v + woff[wid] + sbase;
        g_off[i] = excl;
        g_cnt[i] = excl;  // cursor for fill
    }
}

// ---------------------------------------------------------------------------
// Kernel: fill CSR slots. pos = cursor[dst]++, csr[pos] = src.
// ---------------------------------------------------------------------------
__global__ __launch_bounds__(512) void fill_kernel(const void* __restrict__ ei) {
    int e = blockIdx.x * blockDim.x + threadIdx.x;
    if (e >= N_EDGES) return;
    int s, d;
    if (g_idx_is64) {
        const long long* p = (const long long*)ei;
        s = (int)__ldg(&p[e]);
        d = (int)__ldg(&p[N_EDGES + e]);
    } else {
        const int* p = (const int*)ei;
        s = __ldg(&p[e]);
        d = __ldg(&p[N_EDGES + e]);
    }
    int pos = atomicAdd(&g_cnt[d], 1);
    g_csr[pos] = s;
}

// ---------------------------------------------------------------------------
// Kernel: fused gather + MLP.
// Block = 256 threads, tile = 64 nodes.
// Gather: CONVERGENT warp-cooperative. The whole warp works one node at a
//   time; lane = (half, chunk). Each iteration consumes 2 neighbors:
//   half 0 -> neighbor j, half 1 -> neighbor j+1, lane loads one float4 of
//   its neighbor's row. Trip count is uniform across the warp. Halves are
//   folded with 4 shfl_xor(16) at the end; half 0 stores into hs.
// MLP: register-tiled 4x4 per thread, math in packed f32x2 FFMA2.
// ---------------------------------------------------------------------------
#define HS_STRIDE 68  // 64 + 4 pad; multiple of 4 keeps float4 alignment

__global__ __launch_bounds__(256) void gmlp_kernel(
    const float* __restrict__ x,
    const float* __restrict__ W1, const float* __restrict__ b1,
    const float* __restrict__ W2, const float* __restrict__ b2,
    float* __restrict__ out)
{
    __shared__ float W1s[D * D];
    __shared__ float W2s[D * D];
    __shared__ float hs[64][HS_STRIDE];

    const int tid = threadIdx.x;
    const int node_base = blockIdx.x * 64;
    const float4* __restrict__ x4 = (const float4*)x;

    // Stage weights (float4), covered by the barrier after gather.
    #pragma unroll
    for (int i = tid; i < D * D / 4; i += 256) {
        reinterpret_cast<float4*>(W1s)[i] = reinterpret_cast<const float4*>(W1)[i];
        reinterpret_cast<float4*>(W2s)[i] = reinterpret_cast<const float4*>(W2)[i];
    }

    // ---- Phase 1: gather h = x[n] + sum_{src in N(n)} x[src] ----
    {
        const int warp  = tid >> 5;   // 0..7, each owns 8 nodes
        const int lane  = tid & 31;
        const int half  = lane >> 4;  // 0 or 1
        const int chunk = lane & 15;  // float4 chunk within row

        #pragma unroll 1
        for (int i = 0; i < 8; i++) {
            int nd = warp * 8 + i;
            int g = node_base + nd;

            float4 a = make_float4(0.f, 0.f, 0.f, 0.f);
            if (g < N_NODES) {
                int beg = g_off[g];
                int end = g_off[g + 1];

                // half 0 seeds with the self row; half 1 starts at zero.
                if (half == 0) a = x4[(size_t)g * 16 + chunk];

                int j = beg + half;
                // 2x unroll: 4 neighbors per warp iteration.
                for (; j + 2 < end; j += 4) {
                    int s0 = g_csr[j];
                    int s1 = g_csr[j + 2];
                    float4 v0 = x4[(size_t)s0 * 16 + chunk];
                    float4 v1 = x4[(size_t)s1 * 16 + chunk];
                    a.x += v0.x + v1.x;
                    a.y += v0.y + v1.y;
                    a.z += v0.z + v1.z;
                    a.w += v0.w + v1.w;
                }
                if (j < end) {
                    int s0 = g_csr[j];
                    float4 v0 = x4[(size_t)s0 * 16 + chunk];
                    a.x += v0.x; a.y += v0.y; a.z += v0.z; a.w += v0.w;
                }
            }

            // fold halves
            a.x += __shfl_xor_sync(0xffffffffu, a.x, 16);
            a.y += __shfl_xor_sync(0xffffffffu, a.y, 16);
            a.z += __shfl_xor_sync(0xffffffffu, a.z, 16);
            a.w += __shfl_xor_sync(0xffffffffu, a.w, 16);

            if (half == 0) {
                *reinterpret_cast<float4*>(&hs[nd][chunk * 4]) = a;
            }
        }
    }
    __syncthreads();

    // ---- Phase 2: MLP (f32x2 packed) ----
    const int tx = tid & 15;
    const int ty = tid >> 4;
    ull a01[4], a23[4];

    // Layer 1: t = relu(h @ W1 + b1)
    {
        float4 bv = reinterpret_cast<const float4*>(b1)[tx];
        ull b01 = pk2(bv.x, bv.y), b23 = pk2(bv.z, bv.w);
        #pragma unroll
        for (int r = 0; r < 4; r++) { a01[r] = b01; a23[r] = b23; }
    }
    #pragma unroll 4
    for (int k0 = 0; k0 < D; k0 += 4) {
        float hr[4][4];
        #pragma unroll
        for (int r = 0; r < 4; r++) {
            *reinterpret_cast<float4*>(hr[r]) =
                *reinterpret_cast<const float4*>(&hs[ty * 4 + r][k0]);
        }
        #pragma unroll
        for (int kk = 0; kk < 4; kk++) {
            float4 w = *reinterpret_cast<const float4*>(&W1s[(k0 + kk) * D + tx * 4]);
            ull w01 = pk2(w.x, w.y), w23 = pk2(w.z, w.w);
            #pragma unroll
            for (int r = 0; r < 4; r++) {
                ull hh = pk2(hr[r][kk], hr[r][kk]);
                FMA2(a01[r], hh, w01);
                FMA2(a23[r], hh, w23);
            }
        }
    }
    __syncthreads();

    // ReLU, write t back into hs.
    #pragma unroll
    for (int r = 0; r < 4; r++) {
        float t0, t1, t2, t3;
        upk2(t0, t1, a01[r]);
        upk2(t2, t3, a23[r]);
        float4 t = make_float4(fmaxf(t0, 0.f), fmaxf(t1, 0.f),
                               fmaxf(t2, 0.f), fmaxf(t3, 0.f));
        *reinterpret_cast<float4*>(&hs[ty * 4 + r][tx * 4]) = t;
    }
    __syncthreads();

    // Layer 2: out = t @ W2 + b2
    {
        float4 bv = reinterpret_cast<const float4*>(b2)[tx];
        ull b01 = pk2(bv.x, bv.y), b23 = pk2(bv.z, bv.w);
        #pragma unroll
        for (int r = 0; r < 4; r++) { a01[r] = b01; a23[r] = b23; }
    }
    #pragma unroll 4
    for (int k0 = 0; k0 < D; k0 += 4) {
        float hr[4][4];
        #pragma unroll
        for (int r = 0; r < 4; r++) {
            *reinterpret_cast<float4*>(hr[r]) =
                *reinterpret_cast<const float4*>(&hs[ty * 4 + r][k0]);
        }
        #pragma unroll
        for (int kk = 0; kk < 4; kk++) {
            float4 w = *reinterpret_cast<const float4*>(&W2s[(k0 + kk) * D + tx * 4]);
            ull w01 = pk2(w.x, w.y), w23 = pk2(w.z, w.w);
            #pragma unroll
            for (int r = 0; r < 4; r++) {
                ull hh = pk2(hr[r][kk], hr[r][kk]);
                FMA2(a01[r], hh, w01);
                FMA2(a23[r], hh, w23);
            }
        }
    }

    #pragma unroll
    for (int r = 0; r < 4; r++) {
        int g = node_base + ty * 4 + r;
        if (g < N_NODES) {
            float o0, o1, o2, o3;
            upk2(o0, o1, a01[r]);
            upk2(o2, o3, a23[r]);
            reinterpret_cast<float4*>(out)[(size_t)g * 16 + tx] =
                make_float4(o0, o1, o2, o3);
        }
    }
}

// ---------------------------------------------------------------------------
// Launch. Inputs (metadata order): x, edge_index, W1, b1, W2, b2
// ---------------------------------------------------------------------------
extern "C" void kernel_launch(void* const* d_in, const int* in_sizes, int n_in,
                              void* d_out, int out_size) {
    const float* x  = (const float*)d_in[0];
    const void*  ei = d_in[1];
    const float* W1 = (const float*)d_in[2];
    const float* b1 = (const float*)d_in[3];
    const float* W2 = (const float*)d_in[4];
    const float* b2 = (const float*)d_in[5];
    float* out = (float*)d_out;

    init_kernel<<<(N_NODES + 255) / 256, 256>>>((const int*)ei);

    int eblocks = (N_EDGES + 511) / 512;
    hist_kernel<<<eblocks, 512>>>(ei);

    scanA_kernel<<<NB, 512>>>();
    scanC_kernel<<<NB, 512>>>();

    fill_kernel<<<eblocks, 512>>>(ei);

    gmlp_kernel<<<(N_NODES + 63) / 64, 256>>>(x, W1, b1, W2, b2, out);
}

// round 7
// speedup vs baseline: 1.1033x; 1.1033x over previous
#include <cuda_runtime.h>
#include <cstdint>

#define N_NODES 100000
#define N_EDGES 1250000
#define D 64
#define NB 196        // ceil(N_NODES / 512) scan blocks
#define IDX_CAP 2048  // staged CSR indices per 64-node tile (mean ~800)

typedef unsigned long long ull;

// ---- device scratch (no allocation allowed) ----
__device__ int g_cnt[N_NODES];       // histogram, then fill cursor
__device__ int g_off[N_NODES + 1];   // CSR offsets
__device__ int g_csr[N_EDGES];       // src node per CSR slot
__device__ int g_bsum[NB];           // scan block sums
__device__ int g_idx_is64;

// ---- f32x2 helpers ----
__device__ __forceinline__ ull pk2(float lo, float hi) {
    ull r;
    asm("mov.b64 %0, {%1, %2};" : "=l"(r) : "f"(lo), "f"(hi));
    return r;
}
__device__ __forceinline__ void upk2(float& lo, float& hi, ull v) {
    asm("mov.b64 {%0, %1}, %2;" : "=f"(lo), "=f"(hi) : "l"(v));
}
#define FMA2(acc, a, b) \
    asm("fma.rn.f32x2 %0, %1, %2, %3;" : "=l"(acc) : "l"(a), "l"(b), "l"(acc))

// ---------------------------------------------------------------------------
// Kernel: zero counters, set g_off[N], detect edge_index dtype.
// int64 little-endian => every odd 32-bit word of values < 100000 is zero.
// ---------------------------------------------------------------------------
__global__ __launch_bounds__(512) void init_kernel(const int* __restrict__ ei32) {
    int i = blockIdx.x * blockDim.x + threadIdx.x;
    if (i < N_NODES) g_cnt[i] = 0;
    if (blockIdx.x == 0 && threadIdx.x == 0) {
        g_off[N_NODES] = N_EDGES;
        int is64 = 1;
        #pragma unroll 1
        for (int k = 1; k < 128; k += 2) {
            if (ei32[k] != 0) { is64 = 0; break; }
        }
        g_idx_is64 = is64;
    }
}

// ---------------------------------------------------------------------------
// Kernel: histogram of dst.
// ---------------------------------------------------------------------------
__global__ __launch_bounds__(512) void hist_kernel(const void* __restrict__ ei) {
    int e = blockIdx.x * blockDim.x + threadIdx.x;
    if (e >= N_EDGES) return;
    int d;
    if (g_idx_is64) d = (int)__ldg(&((const long long*)ei)[N_EDGES + e]);
    else            d = __ldg(&((const int*)ei)[N_EDGES + e]);
    atomicAdd(&g_cnt[d], 1);
}

// ---------------------------------------------------------------------------
// Scan A: per-512-block sums (warp shuffles).
// ---------------------------------------------------------------------------
__global__ __launch_bounds__(512) void scanA_kernel() {
    __shared__ int wsum[16];
    int t = threadIdx.x;
    int i = blockIdx.x * 512 + t;
    int v = (i < N_NODES) ? g_cnt[i] : 0;
    #pragma unroll
    for (int o = 16; o; o >>= 1) v += __shfl_down_sync(0xffffffffu, v, o);
    if ((t & 31) == 0) wsum[t >> 5] = v;
    __syncthreads();
    if (t < 16) {
        int s = wsum[t];
        #pragma unroll
        for (int o = 8; o; o >>= 1) s += __shfl_down_sync(0xffffu, s, o);
        if (t == 0) g_bsum[blockIdx.x] = s;
    }
}

// ---------------------------------------------------------------------------
// Scan C: base = sum(g_bsum[0..bid)) + local exclusive scan, shuffle-based.
// ---------------------------------------------------------------------------
__global__ __launch_bounds__(512) void scanC_kernel() {
    __shared__ int wsum[16];
    __shared__ int woff[16];
    __shared__ int sbase;
    int t = threadIdx.x, bid = blockIdx.x;
    int lane = t & 31, wid = t >> 5;
    int i = bid * 512 + t;

    int bv = (t < bid) ? g_bsum[t] : 0;  // bid <= 195 < 512
    #pragma unroll
    for (int o = 16; o; o >>= 1) bv += __shfl_down_sync(0xffffffffu, bv, o);
    if (lane == 0) wsum[wid] = bv;
    __syncthreads();
    if (t < 16) {
        int s = wsum[t];
        #pragma unroll
        for (int o = 8; o; o >>= 1) s += __shfl_down_sync(0xffffu, s, o);
        if (t == 0) sbase = s;
    }
    __syncthreads();

    int v = (i < N_NODES) ? g_cnt[i] : 0;
    int xi = v;
    #pragma unroll
    for (int o = 1; o < 32; o <<= 1) {
        int y = __shfl_up_sync(0xffffffffu, xi, o);
        if (lane >= o) xi += y;
    }
    if (lane == 31) wsum[wid] = xi;
    __syncthreads();
    if (t < 16) {
        int s = wsum[t];
        int si = s;
        #pragma unroll
        for (int o = 1; o < 16; o <<= 1) {
            int y = __shfl_up_sync(0xffffu, si, o);
            if (t >= o) si += y;
        }
        woff[t] = si - s;
    }
    __syncthreads();
    if (i < N_NODES) {
        int excl = xi - v + woff[wid] + sbase;
        g_off[i] = excl;
        g_cnt[i] = excl;  // cursor for fill
    }
}

// ---------------------------------------------------------------------------
// Kernel: fill CSR slots. pos = cursor[dst]++, csr[pos] = src.
// ---------------------------------------------------------------------------
__global__ __launch_bounds__(512) void fill_kernel(const void* __restrict__ ei) {
    int e = blockIdx.x * blockDim.x + threadIdx.x;
    if (e >= N_EDGES) return;
    int s, d;
    if (g_idx_is64) {
        const long long* p = (const long long*)ei;
        s = (int)__ldg(&p[e]);
        d = (int)__ldg(&p[N_EDGES + e]);
    } else {
        const int* p = (const int*)ei;
        s = __ldg(&p[e]);
        d = __ldg(&p[N_EDGES + e]);
    }
    int pos = atomicAdd(&g_cnt[d], 1);
    g_csr[pos] = s;
}

// ---------------------------------------------------------------------------
// Kernel: fused gather + MLP.
// Block = 256 threads, tile = 64 nodes.
// Stage 0: cooperatively stage W1 and the tile's CONTIGUOUS CSR index range
//          into smem (coalesced).
// Gather:  half-warp per node (R5 scheme), neighbor loop unrolled x4 with
//          indices from smem (LDS 29cyc replaces LDG ~250cyc in the chain).
// MLP:     register-tiled 4x4 per thread, packed f32x2 FFMA2; W2 staged into
//          the same smem buffer during the ReLU-writeback barrier window.
// ---------------------------------------------------------------------------
#define HS_STRIDE 68  // 64 + 4 pad; multiple of 4 keeps float4 alignment

__global__ __launch_bounds__(256) void gmlp_kernel(
    const float* __restrict__ x,
    const float* __restrict__ W1, const float* __restrict__ b1,
    const float* __restrict__ W2, const float* __restrict__ b2,
    float* __restrict__ out)
{
    __shared__ float Ws[D * D];          // 16 KB, reused for W1 then W2
    __shared__ float hs[64][HS_STRIDE];  // 17.4 KB
    __shared__ int idx_s[IDX_CAP];       // 8 KB
    __shared__ int tinfo[2];             // tile_beg, tile_edges

    const int tid = threadIdx.x;
    const int node_base = blockIdx.x * 64;
    const float4* __restrict__ x4 = (const float4*)x;

    // Stage W1 (float4).
    #pragma unroll
    for (int i = tid; i < D * D / 4; i += 256) {
        reinterpret_cast<float4*>(Ws)[i] = reinterpret_cast<const float4*>(W1)[i];
    }

    // Stage the tile's CSR index range.
    if (tid == 0) {
        int tb = g_off[node_base];
        int te_node = node_base + 64;
        if (te_node > N_NODES) te_node = N_NODES;
        int ne = g_off[te_node] - tb;
        tinfo[0] = tb;
        tinfo[1] = ne;
    }
    __syncthreads();
    const int tile_beg = tinfo[0];
    {
        int ne = tinfo[1];
        int lim = ne < IDX_CAP ? ne : IDX_CAP;
        for (int i = tid; i < lim; i += 256) {
            idx_s[i] = g_csr[tile_beg + i];
        }
    }
    __syncthreads();

    // ---- Phase 1: gather h = x[n] + sum_{src in N(n)} x[src] ----
    {
        const int hw = tid >> 4;   // half-warp id 0..15, 4 nodes each
        const int hl = tid & 15;   // float4 chunk within row
        #pragma unroll 1
        for (int i = 0; i < 4; i++) {
            int nd = hw * 4 + i;
            int g = node_base + nd;
            float4 a = make_float4(0.f, 0.f, 0.f, 0.f);
            if (g < N_NODES) {
                a = x4[(size_t)g * 16 + hl];
                int lbeg = g_off[g] - tile_beg;
                int lend = g_off[g + 1] - tile_beg;
                if (lend <= IDX_CAP) {
                    // fast path: indices from smem
                    int j = lbeg;
                    for (; j + 3 < lend; j += 4) {
                        int s0 = idx_s[j];
                        int s1 = idx_s[j + 1];
                        int s2 = idx_s[j + 2];
                        int s3 = idx_s[j + 3];
                        float4 v0 = x4[(size_t)s0 * 16 + hl];
                        float4 v1 = x4[(size_t)s1 * 16 + hl];
                        float4 v2 = x4[(size_t)s2 * 16 + hl];
                        float4 v3 = x4[(size_t)s3 * 16 + hl];
                        a.x += v0.x + v1.x + v2.x + v3.x;
                        a.y += v0.y + v1.y + v2.y + v3.y;
                        a.z += v0.z + v1.z + v2.z + v3.z;
                        a.w += v0.w + v1.w + v2.w + v3.w;
                    }
                    for (; j < lend; j++) {
                        int s0 = idx_s[j];
                        float4 v0 = x4[(size_t)s0 * 16 + hl];
                        a.x += v0.x; a.y += v0.y; a.z += v0.z; a.w += v0.w;
                    }
                } else {
                    // cold path: indices from global (tile overflow; ~never)
                    int j = tile_beg + lbeg;
                    int end = tile_beg + lend;
                    for (; j < end; j++) {
                        int s0 = g_csr[j];
                        float4 v0 = x4[(size_t)s0 * 16 + hl];
                        a.x += v0.x; a.y += v0.y; a.z += v0.z; a.w += v0.w;
                    }
                }
            }
            *reinterpret_cast<float4*>(&hs[nd][hl * 4]) = a;
        }
    }
    __syncthreads();

    // ---- Phase 2: MLP (f32x2 packed) ----
    const int tx = tid & 15;
    const int ty = tid >> 4;
    ull a01[4], a23[4];

    // Layer 1: t = relu(h @ W1 + b1)
    {
        float4 bv = reinterpret_cast<const float4*>(b1)[tx];
        ull b01 = pk2(bv.x, bv.y), b23 = pk2(bv.z, bv.w);
        #pragma unroll
        for (int r = 0; r < 4; r++) { a01[r] = b01; a23[r] = b23; }
    }
    #pragma unroll 4
    for (int k0 = 0; k0 < D; k0 += 4) {
        float hr[4][4];
        #pragma unroll
        for (int r = 0; r < 4; r++) {
            *reinterpret_cast<float4*>(hr[r]) =
                *reinterpret_cast<const float4*>(&hs[ty * 4 + r][k0]);
        }
        #pragma unroll
        for (int kk = 0; kk < 4; kk++) {
            float4 w = *reinterpret_cast<const float4*>(&Ws[(k0 + kk) * D + tx * 4]);
            ull w01 = pk2(w.x, w.y), w23 = pk2(w.z, w.w);
            #pragma unroll
            for (int r = 0; r < 4; r++) {
                ull hh = pk2(hr[r][kk], hr[r][kk]);
                FMA2(a01[r], hh, w01);
                FMA2(a23[r], hh, w23);
            }
        }
    }
    __syncthreads();  // layer-1 reads of Ws and hs complete

    // ReLU write-back into hs + stage W2 into Ws (same barrier window).
    #pragma unroll
    for (int r = 0; r < 4; r++) {
        float t0, t1, t2, t3;
        upk2(t0, t1, a01[r]);
        upk2(t2, t3, a23[r]);
        float4 t = make_float4(fmaxf(t0, 0.f), fmaxf(t1, 0.f),
                               fmaxf(t2, 0.f), fmaxf(t3, 0.f));
        *reinterpret_cast<float4*>(&hs[ty * 4 + r][tx * 4]) = t;
    }
    #pragma unroll
    for (int i = tid; i < D * D / 4; i += 256) {
        reinterpret_cast<float4*>(Ws)[i] = reinterpret_cast<const float4*>(W2)[i];
    }
    __syncthreads();

    // Layer 2: out = t @ W2 + b2
    {
        float4 bv = reinterpret_cast<const float4*>(b2)[tx];
        ull b01 = pk2(bv.x, bv.y), b23 = pk2(bv.z, bv.w);
        #pragma unroll
        for (int r = 0; r < 4; r++) { a01[r] = b01; a23[r] = b23; }
    }
    #pragma unroll 4
    for (int k0 = 0; k0 < D; k0 += 4) {
        float hr[4][4];
        #pragma unroll
        for (int r = 0; r < 4; r++) {
            *reinterpret_cast<float4*>(hr[r]) =
                *reinterpret_cast<const float4*>(&hs[ty * 4 + r][k0]);
        }
        #pragma unroll
        for (int kk = 0; kk < 4; kk++) {
            float4 w = *reinterpret_cast<const float4*>(&Ws[(k0 + kk) * D + tx * 4]);
            ull w01 = pk2(w.x, w.y), w23 = pk2(w.z, w.w);
            #pragma unroll
            for (int r = 0; r < 4; r++) {
                ull hh = pk2(hr[r][kk], hr[r][kk]);
                FMA2(a01[r], hh, w01);
                FMA2(a23[r], hh, w23);
            }
        }
    }

    #pragma unroll
    for (int r = 0; r < 4; r++) {
        int g = node_base + ty * 4 + r;
        if (g < N_NODES) {
            float o0, o1, o2, o3;
            upk2(o0, o1, a01[r]);
            upk2(o2, o3, a23[r]);
            reinterpret_cast<float4*>(out)[(size_t)g * 16 + tx] =
                make_float4(o0, o1, o2, o3);
        }
    }
}

// ---------------------------------------------------------------------------
// Launch. Inputs (metadata order): x, edge_index, W1, b1, W2, b2
// ---------------------------------------------------------------------------
extern "C" void kernel_launch(void* const* d_in, const int* in_sizes, int n_in,
                              void* d_out, int out_size) {
    const float* x  = (const float*)d_in[0];
    const void*  ei = d_in[1];
    const float* W1 = (const float*)d_in[2];
    const float* b1 = (const float*)d_in[3];
    const float* W2 = (const float*)d_in[4];
    const float* b2 = (const float*)d_in[5];
    float* out = (float*)d_out;

    init_kernel<<<(N_NODES + 511) / 512, 512>>>((const int*)ei);

    int eblocks = (N_EDGES + 511) / 512;
    hist_kernel<<<eblocks, 512>>>(ei);

    scanA_kernel<<<NB, 512>>>();
    scanC_kernel<<<NB, 512>>>();

    fill_kernel<<<eblocks, 512>>>(ei);

    gmlp_kernel<<<(N_NODES + 63) / 64, 256>>>(x, W1, b1, W2, b2, out);
}